// round 1
// baseline (speedup 1.0000x reference)
#include <cuda_runtime.h>
#include <cuda_bf16.h>

#define B_ 4
#define S_ 2048
#define H_ 8
#define D_ 64
#define DM_ 512

// ---------------- device scratch (no cudaMalloc allowed) ----------------
__device__ float g_q[B_ * H_ * S_ * D_];      // [B][H][S][D]
__device__ float g_k[B_ * H_ * S_ * D_];
__device__ float g_v[B_ * H_ * S_ * D_];
__device__ float g_bias[(size_t)B_ * S_ * S_]; // [B][S][S] gathered gene bias
__device__ float g_ctx[B_ * S_ * DM_];         // [B][S][DM] attention output

// ============================================================
// Kernel 1: QKV projection.  qkv[m][n] = sum_k A[m][k]*W[n][k] + bias[n]
// M=8192 (B*S), N=1536, K=512.  Writes q/k/v directly in [B][H][S][D].
// 128x128 tile, BK=16, 256 threads, 8x8 microtile.
// ============================================================
__global__ __launch_bounds__(256) void qkv_gemm_kernel(
    const float* __restrict__ A, const float* __restrict__ W,
    const float* __restrict__ bias)
{
    __shared__ __align__(16) float As[16][128];
    __shared__ __align__(16) float Bs[16][128];
    const int bm = blockIdx.y * 128;
    const int bn = blockIdx.x * 128;
    const int tid = threadIdx.x;
    const int tx = tid & 15, ty = tid >> 4;
    const int lr = tid >> 2;
    const int lc = (tid & 3) << 2;

    float acc[8][8];
#pragma unroll
    for (int i = 0; i < 8; i++)
#pragma unroll
        for (int j = 0; j < 8; j++) acc[i][j] = 0.f;

    for (int kt = 0; kt < 512; kt += 16) {
        float4 a0 = *(const float4*)&A[(size_t)(bm + lr) * 512 + kt + lc];
        float4 a1 = *(const float4*)&A[(size_t)(bm + lr + 64) * 512 + kt + lc];
        float4 b0 = *(const float4*)&W[(size_t)(bn + lr) * 512 + kt + lc];
        float4 b1 = *(const float4*)&W[(size_t)(bn + lr + 64) * 512 + kt + lc];
        As[lc + 0][lr] = a0.x; As[lc + 1][lr] = a0.y; As[lc + 2][lr] = a0.z; As[lc + 3][lr] = a0.w;
        As[lc + 0][lr + 64] = a1.x; As[lc + 1][lr + 64] = a1.y; As[lc + 2][lr + 64] = a1.z; As[lc + 3][lr + 64] = a1.w;
        Bs[lc + 0][lr] = b0.x; Bs[lc + 1][lr] = b0.y; Bs[lc + 2][lr] = b0.z; Bs[lc + 3][lr] = b0.w;
        Bs[lc + 0][lr + 64] = b1.x; Bs[lc + 1][lr + 64] = b1.y; Bs[lc + 2][lr + 64] = b1.z; Bs[lc + 3][lr + 64] = b1.w;
        __syncthreads();
#pragma unroll
        for (int kk = 0; kk < 16; kk++) {
            float4 av0 = ((const float4*)As[kk])[ty * 2];
            float4 av1 = ((const float4*)As[kk])[ty * 2 + 1];
            float4 bv0 = ((const float4*)Bs[kk])[tx * 2];
            float4 bv1 = ((const float4*)Bs[kk])[tx * 2 + 1];
            float av[8] = {av0.x, av0.y, av0.z, av0.w, av1.x, av1.y, av1.z, av1.w};
            float bv[8] = {bv0.x, bv0.y, bv0.z, bv0.w, bv1.x, bv1.y, bv1.z, bv1.w};
#pragma unroll
            for (int i = 0; i < 8; i++)
#pragma unroll
                for (int j = 0; j < 8; j++) acc[i][j] += av[i] * bv[j];
        }
        __syncthreads();
    }

    // epilogue: scatter into g_q / g_k / g_v, [B][H][S][D]
#pragma unroll
    for (int i = 0; i < 8; i++) {
        const int m = bm + ty * 8 + i;
        const int bb = m >> 11, s = m & 2047;
#pragma unroll
        for (int jj = 0; jj < 8; jj += 4) {
            const int n = bn + tx * 8 + jj;
            const int part = n >> 9;
            const int h = (n >> 6) & 7;
            const int d = n & 63;
            float* dst = (part == 0) ? g_q : ((part == 1) ? g_k : g_v);
            float4 v;
            v.x = acc[i][jj + 0] + bias[n + 0];
            v.y = acc[i][jj + 1] + bias[n + 1];
            v.z = acc[i][jj + 2] + bias[n + 2];
            v.w = acc[i][jj + 3] + bias[n + 3];
            *(float4*)&dst[((size_t)((bb * 8 + h) * 2048 + s)) * 64 + d] = v;
        }
    }
}

// ============================================================
// Kernel 2: gene bias gather.  g_bias[b][q][k] = gene_bias[gi[b][q]][gi[b][k]]
// ============================================================
__global__ __launch_bounds__(256) void bias_gather_kernel(
    const int* __restrict__ gi, const float* __restrict__ gb)
{
    __shared__ int cols[2048];
    const int b = blockIdx.y;
    const int qbase = blockIdx.x * 16;
    for (int i = threadIdx.x; i < 2048; i += 256) cols[i] = gi[b * 2048 + i];
    __syncthreads();
    float* dst = g_bias + ((size_t)b * 2048 + qbase) * 2048;
    for (int q = 0; q < 16; q++) {
        const float* src = gb + (size_t)cols[qbase + q] * 8192;
        float* drow = dst + (size_t)q * 2048;
        for (int k = threadIdx.x * 4; k < 2048; k += 1024) {
            float4 v;
            v.x = src[cols[k + 0]];
            v.y = src[cols[k + 1]];
            v.z = src[cols[k + 2]];
            v.w = src[cols[k + 3]];
            *(float4*)&drow[k] = v;
        }
    }
}

// ============================================================
// Kernel 3: flash attention.  grid (32 q-tiles, 8 heads, 4 batch), 256 thr.
// Q tile 64x64 in smem; K stored transposed w/ XOR swizzle; P reuses K buffer.
// Each warp owns 8 q-rows; lane owns columns {lane, lane+32}.
// ============================================================
__global__ __launch_bounds__(256) void attn_kernel()
{
    __shared__ float Qs[64 * 64];
    __shared__ float KtSs[64 * 64];  // phase A: K^T (swizzled); phase B: P tile
    __shared__ float Vs[64 * 64];

    const int qt = blockIdx.x, h = blockIdx.y, b = blockIdx.z;
    const int tid = threadIdx.x;
    const int warp = tid >> 5, lane = tid & 31;
    const int r0 = warp * 8;

    const float* Qg = g_q + ((size_t)((b * 8 + h) * 2048 + qt * 64)) * 64;
    const float* Kg = g_k + ((size_t)((b * 8 + h) * 2048)) * 64;
    const float* Vg = g_v + ((size_t)((b * 8 + h) * 2048)) * 64;
    const float* Bg = g_bias + ((size_t)(b * 2048 + qt * 64)) * 2048;

#pragma unroll
    for (int i = tid; i < 1024; i += 256)
        ((float4*)Qs)[i] = ((const float4*)Qg)[i];

    float m_i[8], l_i[8], o0[8], o1[8];
#pragma unroll
    for (int r = 0; r < 8; r++) { m_i[r] = -1e30f; l_i[r] = 0.f; o0[r] = 0.f; o1[r] = 0.f; }

    for (int kt2 = 0; kt2 < 32; kt2++) {
        __syncthreads();  // everyone done with previous tile's KtSs / Vs
        const float* Ktile = Kg + kt2 * 4096;
        const float* Vtile = Vg + kt2 * 4096;
#pragma unroll
        for (int i = tid; i < 4096; i += 256) {
            int c = i >> 6, d = i & 63;
            KtSs[(d << 6) + (c ^ (d & 31))] = Ktile[i];  // K^T, xor-swizzled
        }
#pragma unroll
        for (int i = tid; i < 1024; i += 256)
            ((float4*)Vs)[i] = ((const float4*)Vtile)[i];

        // prefetch bias for this tile (overlaps with GEMM1)
        const int kcol = (kt2 << 6) + lane;
        float bv0[8], bv1[8];
#pragma unroll
        for (int r = 0; r < 8; r++) {
            bv0[r] = Bg[(size_t)(r0 + r) * 2048 + kcol];
            bv1[r] = Bg[(size_t)(r0 + r) * 2048 + kcol + 32];
        }
        __syncthreads();

        // ---- GEMM1: S = Q K^T (per warp: 8 rows x 64 cols) ----
        float s0[8], s1[8];
#pragma unroll
        for (int r = 0; r < 8; r++) { s0[r] = 0.f; s1[r] = 0.f; }
#pragma unroll 16
        for (int d = 0; d < 64; d++) {
            const int sw = (d << 6) + (lane ^ (d & 31));
            float k0 = KtSs[sw];
            float k1 = KtSs[sw + 32];
#pragma unroll
            for (int r = 0; r < 8; r++) {
                float q = Qs[((r0 + r) << 6) + d];
                s0[r] += q * k0;
                s1[r] += q * k1;
            }
        }
        __syncthreads();  // all warps done reading K^T; buffer becomes P

        // ---- softmax (online) + write P ----
#pragma unroll
        for (int r = 0; r < 8; r++) {
            float sc0 = s0[r] * 0.125f + bv0[r];
            float sc1 = s1[r] * 0.125f + bv1[r];
            float mx = fmaxf(sc0, sc1);
#pragma unroll
            for (int off = 16; off > 0; off >>= 1)
                mx = fmaxf(mx, __shfl_xor_sync(0xffffffffu, mx, off));
            float mnew = fmaxf(m_i[r], mx);
            float corr = __expf(m_i[r] - mnew);
            float p0 = __expf(sc0 - mnew);
            float p1 = __expf(sc1 - mnew);
            float rs = p0 + p1;
#pragma unroll
            for (int off = 16; off > 0; off >>= 1)
                rs += __shfl_xor_sync(0xffffffffu, rs, off);
            m_i[r] = mnew;
            l_i[r] = l_i[r] * corr + rs;
            o0[r] *= corr;
            o1[r] *= corr;
            KtSs[((r0 + r) << 6) + lane] = p0;
            KtSs[((r0 + r) << 6) + lane + 32] = p1;
        }

        // ---- GEMM2: O += P V (own rows only; no sync needed) ----
#pragma unroll 8
        for (int k = 0; k < 64; k++) {
            float v0 = Vs[(k << 6) + lane];
            float v1 = Vs[(k << 6) + lane + 32];
#pragma unroll
            for (int r = 0; r < 8; r++) {
                float p = KtSs[((r0 + r) << 6) + k];
                o0[r] += p * v0;
                o1[r] += p * v1;
            }
        }
    }

    // epilogue: write [B][S][H*64+d]
#pragma unroll
    for (int r = 0; r < 8; r++) {
        float inv = 1.f / l_i[r];
        size_t row = (size_t)(b * 2048 + qt * 64 + r0 + r) * 512 + h * 64;
        g_ctx[row + lane] = o0[r] * inv;
        g_ctx[row + lane + 32] = o1[r] * inv;
    }
}

// ============================================================
// Kernel 4: output projection.  out[m][n] = sum_k ctx[m][k]*Wo[n][k] + ob[n]
// M=8192, N=512, K=512
// ============================================================
__global__ __launch_bounds__(256) void out_gemm_kernel(
    const float* __restrict__ Wo, const float* __restrict__ ob,
    float* __restrict__ C)
{
    __shared__ __align__(16) float As[16][128];
    __shared__ __align__(16) float Bs[16][128];
    const int bm = blockIdx.y * 128;
    const int bn = blockIdx.x * 128;
    const int tid = threadIdx.x;
    const int tx = tid & 15, ty = tid >> 4;
    const int lr = tid >> 2;
    const int lc = (tid & 3) << 2;
    const float* A = g_ctx;

    float acc[8][8];
#pragma unroll
    for (int i = 0; i < 8; i++)
#pragma unroll
        for (int j = 0; j < 8; j++) acc[i][j] = 0.f;

    for (int kt = 0; kt < 512; kt += 16) {
        float4 a0 = *(const float4*)&A[(size_t)(bm + lr) * 512 + kt + lc];
        float4 a1 = *(const float4*)&A[(size_t)(bm + lr + 64) * 512 + kt + lc];
        float4 b0 = *(const float4*)&Wo[(size_t)(bn + lr) * 512 + kt + lc];
        float4 b1 = *(const float4*)&Wo[(size_t)(bn + lr + 64) * 512 + kt + lc];
        As[lc + 0][lr] = a0.x; As[lc + 1][lr] = a0.y; As[lc + 2][lr] = a0.z; As[lc + 3][lr] = a0.w;
        As[lc + 0][lr + 64] = a1.x; As[lc + 1][lr + 64] = a1.y; As[lc + 2][lr + 64] = a1.z; As[lc + 3][lr + 64] = a1.w;
        Bs[lc + 0][lr] = b0.x; Bs[lc + 1][lr] = b0.y; Bs[lc + 2][lr] = b0.z; Bs[lc + 3][lr] = b0.w;
        Bs[lc + 0][lr + 64] = b1.x; Bs[lc + 1][lr + 64] = b1.y; Bs[lc + 2][lr + 64] = b1.z; Bs[lc + 3][lr + 64] = b1.w;
        __syncthreads();
#pragma unroll
        for (int kk = 0; kk < 16; kk++) {
            float4 av0 = ((const float4*)As[kk])[ty * 2];
            float4 av1 = ((const float4*)As[kk])[ty * 2 + 1];
            float4 bv0 = ((const float4*)Bs[kk])[tx * 2];
            float4 bv1 = ((const float4*)Bs[kk])[tx * 2 + 1];
            float av[8] = {av0.x, av0.y, av0.z, av0.w, av1.x, av1.y, av1.z, av1.w};
            float bv[8] = {bv0.x, bv0.y, bv0.z, bv0.w, bv1.x, bv1.y, bv1.z, bv1.w};
#pragma unroll
            for (int i = 0; i < 8; i++)
#pragma unroll
                for (int j = 0; j < 8; j++) acc[i][j] += av[i] * bv[j];
        }
        __syncthreads();
    }

#pragma unroll
    for (int i = 0; i < 8; i++) {
        const int m = bm + ty * 8 + i;
#pragma unroll
        for (int jj = 0; jj < 8; jj += 4) {
            const int n = bn + tx * 8 + jj;
            float4 v;
            v.x = acc[i][jj + 0] + ob[n + 0];
            v.y = acc[i][jj + 1] + ob[n + 1];
            v.z = acc[i][jj + 2] + ob[n + 2];
            v.w = acc[i][jj + 3] + ob[n + 3];
            *(float4*)&C[(size_t)m * 512 + n] = v;
        }
    }
}

// ============================================================
extern "C" void kernel_launch(void* const* d_in, const int* in_sizes, int n_in,
                              void* d_out, int out_size)
{
    const float* query = (const float*)d_in[0];
    const int*   gidx  = (const int*)d_in[1];
    const float* ipw   = (const float*)d_in[2];
    const float* ipb   = (const float*)d_in[3];
    const float* outw  = (const float*)d_in[4];
    const float* outb  = (const float*)d_in[5];
    const float* gbias = (const float*)d_in[6];
    float* out = (float*)d_out;

    qkv_gemm_kernel<<<dim3(12, 64), 256>>>(query, ipw, ipb);
    bias_gather_kernel<<<dim3(128, 4), 256>>>(gidx, gbias);
    attn_kernel<<<dim3(32, 8, 4), 256>>>();
    out_gemm_kernel<<<dim3(4, 64), 256>>>(outw, outb, out);
}